// round 4
// baseline (speedup 1.0000x reference)
#include <cuda_runtime.h>

#define ALPHA 0.2f
#define MASKV -9000000000000000.0f
using ull  = unsigned long long;
using ull2 = ulonglong2;

__constant__ __align__(16) float cW1[96];     // (3,1,32)
__constant__ __align__(16) float cA1[192];    // (3,64,1)
__constant__ __align__(16) float cW2[4608];   // (3,96,16)
__constant__ __align__(16) float cA2[96];     // (3,32,1)
__constant__ __align__(16) float cWp1[1152];  // (48,24)
__constant__ __align__(16) float cBp1[24];
__constant__ __align__(16) float cWp2[24];
__constant__ __align__(16) float cBp2[4];
__constant__ __align__(16) float cAdj[84];

#define NBLK 512
#define NTHR 128
#define NTOT (NBLK*NTHR)

__device__ ull g_vp[288];                    // {v1,v2}[h*96+k]
__device__ ull g_whp[(size_t)216 * NTOT];    // Wh pairs per thread; reused for h2
__device__ ull g_fp[(size_t)27 * NTOT];      // {f1,f2}[h*9+i] per thread

__device__ __forceinline__ void ffma2(ull& d, ull a, ull b) {
    asm("fma.rn.f32x2 %0, %1, %2, %0;" : "+l"(d) : "l"(a), "l"(b));
}
__device__ __forceinline__ ull dup2(float x) {
    ull r; asm("mov.b64 %0, {%1, %1};" : "=l"(r) : "f"(x)); return r;
}
__device__ __forceinline__ ull pack2(float x, float y) {
    ull r; asm("mov.b64 %0, {%1, %2};" : "=l"(r) : "f"(x), "f"(y)); return r;
}
__device__ __forceinline__ float2 unp(ull v) {
    float2 r; asm("mov.b64 {%0, %1}, %2;" : "=f"(r.x), "=f"(r.y) : "l"(v)); return r;
}
__device__ __forceinline__ float tanh_fast(float x) {
    float r; asm("tanh.approx.f32 %0, %1;" : "=f"(r) : "f"(x)); return r;
}
__device__ __forceinline__ ull c64(const float* p) {
    return __double_as_longlong(*(const double*)(const void*)p);
}
__device__ __forceinline__ float lrelu(float x) { return fmaxf(x, ALPHA * x); }

// ---- prep: v-vectors for layer-2 logits ----
__global__ void prep_kernel() {
    for (int idx = threadIdx.x; idx < 288; idx += 128) {
        int h = idx / 96, k = idx - h * 96;
        float v1 = 0.f, v2 = 0.f;
        #pragma unroll
        for (int d = 0; d < 16; d++) {
            float w = cW2[h*1536 + k*16 + d];
            v1 += w * cA2[h*32 + d];
            v2 += w * cA2[h*32 + 16 + d];
        }
        g_vp[idx] = pack2(v1, v2);
    }
}

__global__ void __launch_bounds__(NTHR, 4)
gnn_main(const float* __restrict__ g_obs, float* __restrict__ g_out, int B)
{
    const int gtid = blockIdx.x * NTHR + threadIdx.x;
    ull* whb = g_whp + gtid;
    ull* fpb = g_fp  + gtid;

    // loop-invariant: c1/c2 and adjacency masks (local arrays; rolled indexing)
    float c1[3], c2[3];
    #pragma unroll
    for (int h = 0; h < 3; h++) {
        float a = 0.f, bb = 0.f;
        #pragma unroll 8
        for (int d = 0; d < 32; d++) {
            float w = cW1[h*32 + d];
            a  += w * cA1[h*64 + d];
            bb += w * cA1[h*64 + 32 + d];
        }
        c1[h] = a; c2[h] = bb;
    }
    unsigned mrowl[9];
    for (int i = 0; i < 9; i++) {
        unsigned m = 0;
        for (int j = 0; j < 9; j++)
            if (cAdj[i*9 + j] > 0.f) m |= (1u << j);
        mrowl[i] = m;
    }

    for (int b = gtid; b < B; b += NTOT) {
        // obs into registers (unrolled) + local copy for rolled i-indexing
        float og[9], ol[9];
        #pragma unroll
        for (int n = 0; n < 9; n++) { og[n] = g_obs[b*9 + n]; ol[n] = og[n]; }

        // ---- layer-1 (rank-1 collapse): s1[h][i] into local s1l ----
        float s1l[27];
        #pragma unroll
        for (int h = 0; h < 3; h++) {
            const float c1h = c1[h], c2h = c2[h];
            float g[9];
            #pragma unroll
            for (int j = 0; j < 9; j++) g[j] = c2h * og[j];
            #pragma unroll 1
            for (int i = 0; i < 9; i++) {
                float fi = c1h * ol[i];
                unsigned m = mrowl[i];
                float e[9], mx = -3.0e38f;
                #pragma unroll
                for (int j = 0; j < 9; j++) {
                    float x = lrelu(fi + g[j]);
                    if (!((m >> j) & 1u)) x = MASKV;
                    e[j] = x; mx = fmaxf(mx, x);
                }
                float den = 0.f, num = 0.f;
                #pragma unroll
                for (int j = 0; j < 9; j++) {
                    float p = __expf(e[j] - mx);
                    den += p; num += p * og[j];
                }
                s1l[h*9 + i] = __fdividef(num, den);
            }
        }

        // ---- per-row GEMM passes: Wh[i][48] (24 pairs) + f1/f2 via v-vectors ----
        #pragma unroll 1
        for (int i = 0; i < 9; i++) {
            ull acc[24];
            #pragma unroll
            for (int p = 0; p < 24; p++) acc[p] = 0ull;
            ull fac0 = 0ull, fac1 = 0ull, fac2 = 0ull;
            #pragma unroll
            for (int kh = 0; kh < 3; kh++) {
                const float s = s1l[kh*9 + i];
                #pragma unroll 4
                for (int d = 0; d < 32; d++) {
                    const int k = kh*32 + d;
                    float x = s * cW1[k];
                    x = (x > 0.f) ? x : (__expf(x) - 1.f);   // elu -> h1[i][k]
                    const ull e2 = dup2(x);
                    ffma2(fac0, e2, __ldg(&g_vp[k]));
                    ffma2(fac1, e2, __ldg(&g_vp[96 + k]));
                    ffma2(fac2, e2, __ldg(&g_vp[192 + k]));
                    #pragma unroll
                    for (int q = 0; q < 12; q++) {           // cols 4q..4q+3
                        const ull2 w = *(const ull2*)&cW2[(q >> 2)*1536 + k*16 + (q & 3)*4];
                        ffma2(acc[2*q],     e2, w.x);
                        ffma2(acc[2*q + 1], e2, w.y);
                    }
                }
            }
            #pragma unroll
            for (int p = 0; p < 24; p++) whb[(i*24 + p)*NTOT] = acc[p];
            fpb[(0  + i)*NTOT] = fac0;
            fpb[(9  + i)*NTOT] = fac1;
            fpb[(18 + i)*NTOT] = fac2;
        }

        // ---- attention apply per 4-col tile; h2 overwrites Wh in scratch ----
        float f1h[9], f2h[9], mxr[9], inv[9];
        #pragma unroll 1
        for (int t = 0; t < 12; t++) {
            if ((t & 3) == 0) {                 // new head: refresh f and softmax stats
                const int H = t >> 2;
                #pragma unroll
                for (int i = 0; i < 9; i++) {
                    float2 f = unp(fpb[(H*9 + i)*NTOT]);
                    f1h[i] = f.x; f2h[i] = f.y;
                }
                #pragma unroll
                for (int i = 0; i < 9; i++) {
                    unsigned m = mrowl[i];
                    float e[9], mx = -3.0e38f;
                    #pragma unroll
                    for (int j = 0; j < 9; j++) {
                        float x = lrelu(f1h[i] + f2h[j]);
                        if (!((m >> j) & 1u)) x = MASKV;
                        e[j] = x; mx = fmaxf(mx, x);
                    }
                    float den = 0.f;
                    #pragma unroll
                    for (int j = 0; j < 9; j++) den += __expf(e[j] - mx);
                    mxr[i] = mx; inv[i] = __fdividef(1.f, den);
                }
            }
            ull wt0[9], wt1[9];
            #pragma unroll
            for (int j = 0; j < 9; j++) {
                wt0[j] = whb[(j*24 + 2*t    )*NTOT];
                wt1[j] = whb[(j*24 + 2*t + 1)*NTOT];
            }
            #pragma unroll
            for (int i = 0; i < 9; i++) {
                unsigned m = mrowl[i];
                ull r0 = 0ull, r1 = 0ull;
                #pragma unroll
                for (int j = 0; j < 9; j++) {
                    float x = lrelu(f1h[i] + f2h[j]);
                    if (!((m >> j) & 1u)) x = MASKV;
                    float w = __expf(x - mxr[i]) * inv[i];
                    ull wd = dup2(w);
                    ffma2(r0, wt0[j], wd);
                    ffma2(r1, wt1[j], wd);
                }
                whb[(i*24 + 2*t    )*NTOT] = r0;   // h2 pairs overwrite Wh tile
                whb[(i*24 + 2*t + 1)*NTOT] = r1;
            }
        }

        // ---- pooling scores ----
        float scl[9];
        #pragma unroll 1
        for (int n = 0; n < 9; n++) {
            ull U[12];
            #pragma unroll
            for (int mp = 0; mp < 12; mp++) U[mp] = c64(&cBp1[2*mp]);
            #pragma unroll 2
            for (int cp = 0; cp < 24; cp++) {
                float2 hv = unp(whb[(n*24 + cp)*NTOT]);
                ull hx = dup2(hv.x), hy = dup2(hv.y);
                #pragma unroll
                for (int mq = 0; mq < 6; mq++) {
                    ull2 wa = *(const ull2*)&cWp1[(2*cp    )*24 + 4*mq];
                    ull2 wb = *(const ull2*)&cWp1[(2*cp + 1)*24 + 4*mq];
                    ffma2(U[2*mq],     hx, wa.x);
                    ffma2(U[2*mq + 1], hx, wa.y);
                    ffma2(U[2*mq],     hy, wb.x);
                    ffma2(U[2*mq + 1], hy, wb.y);
                }
            }
            float s = cBp2[0];
            #pragma unroll
            for (int mp = 0; mp < 12; mp++) {
                float2 u = unp(U[mp]);
                s += tanh_fast(u.x) * cWp2[2*mp] + tanh_fast(u.y) * cWp2[2*mp + 1];
            }
            scl[n] = s;
        }

        // softmax over nodes
        float mx = scl[0];
        for (int n = 1; n < 9; n++) mx = fmaxf(mx, scl[n]);
        float den = 0.f;
        float wnl[9];
        for (int n = 0; n < 9; n++) { float p = __expf(scl[n] - mx); wnl[n] = p; den += p; }
        float iv = __fdividef(1.f, den);

        // weighted sum + store
        ull outp[24];
        #pragma unroll
        for (int p = 0; p < 24; p++) outp[p] = 0ull;
        #pragma unroll 1
        for (int n = 0; n < 9; n++) {
            ull wd = dup2(wnl[n] * iv);
            #pragma unroll
            for (int p = 0; p < 24; p++)
                ffma2(outp[p], whb[(n*24 + p)*NTOT], wd);
        }
        #pragma unroll
        for (int p = 0; p < 24; p++)
            *(ull*)&g_out[(size_t)b*48 + 2*p] = outp[p];
    }
}

extern "C" void kernel_launch(void* const* d_in, const int* in_sizes, int n_in,
                              void* d_out, int out_size) {
    const float* obs = (const float*)d_in[0];
    int B = in_sizes[0] / 9;

    cudaMemcpyToSymbolAsync(cAdj, d_in[1],   81 * 4, 0, cudaMemcpyDeviceToDevice);
    cudaMemcpyToSymbolAsync(cW1,  d_in[2],   96 * 4, 0, cudaMemcpyDeviceToDevice);
    cudaMemcpyToSymbolAsync(cA1,  d_in[3],  192 * 4, 0, cudaMemcpyDeviceToDevice);
    cudaMemcpyToSymbolAsync(cW2,  d_in[4], 4608 * 4, 0, cudaMemcpyDeviceToDevice);
    cudaMemcpyToSymbolAsync(cA2,  d_in[5],   96 * 4, 0, cudaMemcpyDeviceToDevice);
    cudaMemcpyToSymbolAsync(cWp1, d_in[6], 1152 * 4, 0, cudaMemcpyDeviceToDevice);
    cudaMemcpyToSymbolAsync(cBp1, d_in[7],   24 * 4, 0, cudaMemcpyDeviceToDevice);
    cudaMemcpyToSymbolAsync(cWp2, d_in[8],   24 * 4, 0, cudaMemcpyDeviceToDevice);
    cudaMemcpyToSymbolAsync(cBp2, d_in[9],    1 * 4, 0, cudaMemcpyDeviceToDevice);

    prep_kernel<<<1, 128>>>();
    gnn_main<<<NBLK, NTHR>>>(obs, (float*)d_out, B);
}

// round 6
// speedup vs baseline: 2.5475x; 2.5475x over previous
#include <cuda_runtime.h>

#define ALPHA 0.2f
#define MASKV -9000000000000000.0f
using ull  = unsigned long long;
using ull2 = ulonglong2;

__constant__ __align__(16) float cW1[96];     // (3,1,32)
__constant__ __align__(16) float cA1[192];    // (3,64,1)
__constant__ __align__(16) float cW2[4608];   // (3,96,16)
__constant__ __align__(16) float cA2[96];     // (3,32,1)
__constant__ __align__(16) float cWp1[1152];  // (48,24)
__constant__ __align__(16) float cBp1[24];
__constant__ __align__(16) float cWp2[24];
__constant__ __align__(16) float cBp2[4];
__constant__ __align__(16) float cAdj[84];

#define NTHR 128
#define MAXBLK 1024
#define NT (MAXBLK*NTHR)
#define SSTR 57   // per-thread smem floats: [0..26]=s1, [27..35]=f1, [36..44]=f2, [45..53]=obs

__device__ float    g_c12[6];                // c1[3], c2[3]
__device__ unsigned g_mrow[9];               // adjacency bitmask per row
__device__ ull      g_wh[(size_t)72  * NT];  // per-head Wh tile (9 rows x 8 pairs)
__device__ ull      g_h2[(size_t)216 * NT];  // h2 pairs (9 rows x 24 pairs)

__device__ __forceinline__ void ffma2(ull& d, ull a, ull b) {
    asm("fma.rn.f32x2 %0, %1, %2, %0;" : "+l"(d) : "l"(a), "l"(b));
}
__device__ __forceinline__ ull dup2(float x) {
    ull r; asm("mov.b64 %0, {%1, %1};" : "=l"(r) : "f"(x)); return r;
}
__device__ __forceinline__ float2 unp(ull v) {
    float2 r; asm("mov.b64 {%0, %1}, %2;" : "=f"(r.x), "=f"(r.y) : "l"(v)); return r;
}
__device__ __forceinline__ float tanh_fast(float x) {
    float r; asm("tanh.approx.f32 %0, %1;" : "=f"(r) : "f"(x)); return r;
}
__device__ __forceinline__ ull c64(const float* p) {
    return __double_as_longlong(*(const double*)(const void*)p);
}
__device__ __forceinline__ float lrelu(float x) { return fmaxf(x, ALPHA * x); }
__device__ __forceinline__ float elu(float x) {
    return (x > 0.f) ? x : (__expf(x) - 1.f);
}

// ---- prep: c1/c2 and adjacency bitmasks ----
__global__ void prep_kernel() {
    int t = threadIdx.x;
    if (t < 6) {                 // g_c12[h]=c1[h], g_c12[3+h]=c2[h]
        int h = t % 3, half = t / 3;
        float s = 0.f;
        #pragma unroll
        for (int d = 0; d < 32; d++)
            s += cW1[h*32 + d] * cA1[h*64 + half*32 + d];
        g_c12[half*3 + h] = s;
    }
    if (t < 9) {
        unsigned m = 0;
        for (int j = 0; j < 9; j++)
            if (cAdj[t*9 + j] > 0.f) m |= (1u << j);
        g_mrow[t] = m;
    }
}

__global__ void __launch_bounds__(NTHR, 4)
gnn_main(const float* __restrict__ g_obs, float* __restrict__ g_out, int B)
{
    __shared__ float sS[NTHR * SSTR];
    const int gtid = blockIdx.x * NTHR + threadIdx.x;
    const int stride = gridDim.x * NTHR;
    float* sT  = sS + threadIdx.x * SSTR;
    ull*   whb = g_wh + gtid;
    ull*   h2b = g_h2 + gtid;

    for (int b = gtid; b < B; b += stride) {

        // ================= layer-1: s1[h][i] for ALL heads (the R5 bug fix) =========
        {
            float og[9];
            #pragma unroll
            for (int n = 0; n < 9; n++) { og[n] = g_obs[b*9 + n]; sT[45 + n] = og[n]; }
            #pragma unroll 1
            for (int h = 0; h < 3; h++) {
                const float c1h = __ldg(&g_c12[h]);
                const float c2h = __ldg(&g_c12[3 + h]);
                float gg[9];
                #pragma unroll
                for (int j = 0; j < 9; j++) gg[j] = c2h * og[j];
                #pragma unroll 1
                for (int i = 0; i < 9; i++) {
                    const unsigned m = __ldg(&g_mrow[i]);
                    const float fi = c1h * sT[45 + i];
                    float e[9], mx = -3.0e38f;
                    #pragma unroll
                    for (int j = 0; j < 9; j++) {
                        float x = lrelu(fi + gg[j]);
                        if (!((m >> j) & 1u)) x = MASKV;
                        e[j] = x; mx = fmaxf(mx, x);
                    }
                    float den = 0.f, num = 0.f;
                    #pragma unroll
                    for (int j = 0; j < 9; j++) {
                        float p = __expf(e[j] - mx);
                        den += p; num += p * og[j];
                    }
                    sT[h*9 + i] = __fdividef(num, den);   // s1[h][i]
                }
            }
        }

        // ================= layer-2 per head =================
        #pragma unroll 1
        for (int H = 0; H < 3; H++) {
            const float* wH = &cW2[H*1536];

            // ---- GEMM in 3-row passes: Wh rows + f1/f2 from acc·a2 ----
            #pragma unroll 1
            for (int g3 = 0; g3 < 9; g3 += 3) {
                ull acc[3][8];
                #pragma unroll
                for (int r = 0; r < 3; r++)
                    #pragma unroll
                    for (int p = 0; p < 8; p++) acc[r][p] = 0ull;

                #pragma unroll 1
                for (int kh = 0; kh < 3; kh++) {
                    const float sA = sT[kh*9 + g3];
                    const float sB = sT[kh*9 + g3 + 1];
                    const float sC = sT[kh*9 + g3 + 2];
                    #pragma unroll 4
                    for (int d = 0; d < 32; d++) {
                        const int k = kh*32 + d;
                        const float w1 = cW1[k];
                        const ull eA = dup2(elu(sA * w1));
                        const ull eB = dup2(elu(sB * w1));
                        const ull eC = dup2(elu(sC * w1));
                        const float* wr = wH + k*16;
                        const ull2 wa = *(const ull2*)(wr);
                        const ull2 wb = *(const ull2*)(wr + 4);
                        const ull2 wc = *(const ull2*)(wr + 8);
                        const ull2 wd = *(const ull2*)(wr + 12);
                        ffma2(acc[0][0], eA, wa.x); ffma2(acc[0][1], eA, wa.y);
                        ffma2(acc[0][2], eA, wb.x); ffma2(acc[0][3], eA, wb.y);
                        ffma2(acc[0][4], eA, wc.x); ffma2(acc[0][5], eA, wc.y);
                        ffma2(acc[0][6], eA, wd.x); ffma2(acc[0][7], eA, wd.y);
                        ffma2(acc[1][0], eB, wa.x); ffma2(acc[1][1], eB, wa.y);
                        ffma2(acc[1][2], eB, wb.x); ffma2(acc[1][3], eB, wb.y);
                        ffma2(acc[1][4], eB, wc.x); ffma2(acc[1][5], eB, wc.y);
                        ffma2(acc[1][6], eB, wd.x); ffma2(acc[1][7], eB, wd.y);
                        ffma2(acc[2][0], eC, wa.x); ffma2(acc[2][1], eC, wa.y);
                        ffma2(acc[2][2], eC, wb.x); ffma2(acc[2][3], eC, wb.y);
                        ffma2(acc[2][4], eC, wc.x); ffma2(acc[2][5], eC, wc.y);
                        ffma2(acc[2][6], eC, wd.x); ffma2(acc[2][7], eC, wd.y);
                    }
                }
                // f1/f2 for these rows (dot finished Wh pairs with a2 halves) + store Wh
                #pragma unroll
                for (int r = 0; r < 3; r++) {
                    float f1 = 0.f, f2 = 0.f;
                    #pragma unroll
                    for (int p = 0; p < 8; p++) {
                        float2 t = unp(acc[r][p]);
                        f1 += t.x * cA2[H*32 + 2*p]      + t.y * cA2[H*32 + 2*p + 1];
                        f2 += t.x * cA2[H*32 + 16 + 2*p] + t.y * cA2[H*32 + 17 + 2*p];
                    }
                    sT[27 + g3 + r] = f1;
                    sT[36 + g3 + r] = f2;
                    #pragma unroll
                    for (int p = 0; p < 8; p++)
                        whb[((g3 + r)*8 + p)*NT] = acc[r][p];
                }
            }

            // ---- attention apply for head H ----
            float f2r[9];
            #pragma unroll
            for (int j = 0; j < 9; j++) f2r[j] = sT[36 + j];

            #pragma unroll 1
            for (int i = 0; i < 9; i++) {
                const unsigned m = __ldg(&g_mrow[i]);
                const float f1i = sT[27 + i];
                float e[9], mx = -3.0e38f;
                #pragma unroll
                for (int j = 0; j < 9; j++) {
                    float x = lrelu(f1i + f2r[j]);
                    if (!((m >> j) & 1u)) x = MASKV;
                    e[j] = x; mx = fmaxf(mx, x);
                }
                float den = 0.f;
                #pragma unroll
                for (int j = 0; j < 9; j++) { e[j] = __expf(e[j] - mx); den += e[j]; }
                const float inv = __fdividef(1.f, den);

                ull h2a[8];
                #pragma unroll
                for (int p = 0; p < 8; p++) h2a[p] = 0ull;
                #pragma unroll
                for (int j = 0; j < 9; j++) {
                    const ull wd = dup2(e[j] * inv);
                    #pragma unroll
                    for (int p = 0; p < 8; p++)
                        ffma2(h2a[p], whb[(j*8 + p)*NT], wd);
                }
                #pragma unroll
                for (int p = 0; p < 8; p++)
                    h2b[(i*24 + H*8 + p)*NT] = h2a[p];
            }
        }

        // ================= pooling (validated in R3/R4) =================
        float scl[9];
        #pragma unroll 1
        for (int n = 0; n < 9; n++) {
            ull U[12];
            #pragma unroll
            for (int mp = 0; mp < 12; mp++) U[mp] = c64(&cBp1[2*mp]);
            #pragma unroll 4
            for (int cp = 0; cp < 24; cp++) {
                float2 hv = unp(h2b[(n*24 + cp)*NT]);
                ull hx = dup2(hv.x), hy = dup2(hv.y);
                #pragma unroll
                for (int mq = 0; mq < 6; mq++) {
                    ull2 wa = *(const ull2*)&cWp1[(2*cp    )*24 + 4*mq];
                    ull2 wb = *(const ull2*)&cWp1[(2*cp + 1)*24 + 4*mq];
                    ffma2(U[2*mq],     hx, wa.x);
                    ffma2(U[2*mq + 1], hx, wa.y);
                    ffma2(U[2*mq],     hy, wb.x);
                    ffma2(U[2*mq + 1], hy, wb.y);
                }
            }
            float s = cBp2[0];
            #pragma unroll
            for (int mp = 0; mp < 12; mp++) {
                float2 u = unp(U[mp]);
                s += tanh_fast(u.x) * cWp2[2*mp] + tanh_fast(u.y) * cWp2[2*mp + 1];
            }
            scl[n] = s;
        }

        // softmax over nodes
        float mx = scl[0];
        #pragma unroll
        for (int n = 1; n < 9; n++) mx = fmaxf(mx, scl[n]);
        float den = 0.f, wnl[9];
        #pragma unroll
        for (int n = 0; n < 9; n++) { float p = __expf(scl[n] - mx); wnl[n] = p; den += p; }
        const float iv = __fdividef(1.f, den);

        // weighted sum + vectorized store
        ull outp[24];
        #pragma unroll
        for (int p = 0; p < 24; p++) outp[p] = 0ull;
        #pragma unroll 1
        for (int n = 0; n < 9; n++) {
            const ull wd = dup2(wnl[n] * iv);
            #pragma unroll
            for (int p = 0; p < 24; p++)
                ffma2(outp[p], h2b[(n*24 + p)*NT], wd);
        }
        #pragma unroll
        for (int p = 0; p < 24; p++)
            *(ull*)&g_out[(size_t)b*48 + 2*p] = outp[p];
    }
}

extern "C" void kernel_launch(void* const* d_in, const int* in_sizes, int n_in,
                              void* d_out, int out_size) {
    const float* obs = (const float*)d_in[0];
    int B = in_sizes[0] / 9;

    cudaMemcpyToSymbolAsync(cAdj, d_in[1],   81 * 4, 0, cudaMemcpyDeviceToDevice);
    cudaMemcpyToSymbolAsync(cW1,  d_in[2],   96 * 4, 0, cudaMemcpyDeviceToDevice);
    cudaMemcpyToSymbolAsync(cA1,  d_in[3],  192 * 4, 0, cudaMemcpyDeviceToDevice);
    cudaMemcpyToSymbolAsync(cW2,  d_in[4], 4608 * 4, 0, cudaMemcpyDeviceToDevice);
    cudaMemcpyToSymbolAsync(cA2,  d_in[5],   96 * 4, 0, cudaMemcpyDeviceToDevice);
    cudaMemcpyToSymbolAsync(cWp1, d_in[6], 1152 * 4, 0, cudaMemcpyDeviceToDevice);
    cudaMemcpyToSymbolAsync(cBp1, d_in[7],   24 * 4, 0, cudaMemcpyDeviceToDevice);
    cudaMemcpyToSymbolAsync(cWp2, d_in[8],   24 * 4, 0, cudaMemcpyDeviceToDevice);
    cudaMemcpyToSymbolAsync(cBp2, d_in[9],    1 * 4, 0, cudaMemcpyDeviceToDevice);

    int blocks = (B + NTHR - 1) / NTHR;
    if (blocks > MAXBLK) blocks = MAXBLK;

    prep_kernel<<<1, 32>>>();
    gnn_main<<<blocks, NTHR>>>(obs, (float*)d_out, B);
}